// round 1
// baseline (speedup 1.0000x reference)
#include <cuda_runtime.h>
#include <math.h>

typedef unsigned long long ull;

// ---------------- f32x2 packed-math helpers (sm_103a) ----------------
__device__ __forceinline__ ull fma2(ull a, ull b, ull c){
    ull d; asm("fma.rn.f32x2 %0, %1, %2, %3;" : "=l"(d) : "l"(a), "l"(b), "l"(c)); return d;
}
__device__ __forceinline__ ull pack2(float x){
    ull r; asm("mov.b64 %0, {%1, %1};" : "=l"(r) : "f"(x)); return r;
}
__device__ __forceinline__ ull packf2(float a, float b){
    ull r; asm("mov.b64 %0, {%1, %2};" : "=l"(r) : "f"(a), "f"(b)); return r;
}
__device__ __forceinline__ float2 unpack2(ull v){
    float2 r; asm("mov.b64 {%0, %1}, %2;" : "=f"(r.x), "=f"(r.y) : "l"(v)); return r;
}

// ---------------- scratch (device globals; no allocations allowed) ----------------
#define MAXN 50048
#define MAXE 800000

__device__ float g_xl[MAXN * 256];
__device__ float g_xr[MAXN * 256];
__device__ float g_h1[MAXN * 128];
__device__ float g_h2[MAXN * 128];
__device__ float g_h3[MAXN * 64];
__device__ float g_asum[MAXN * 16];
__device__ float g_mattr[MAXN * 16];
__device__ float g_gvec[64 * 64];
__device__ int   g_deg[MAXN + 1];
__device__ int   g_rowptr[MAXN + 1];
__device__ int   g_cursor[MAXN];
__device__ int   g_srcs[MAXE];
__device__ int   g_eids[MAXE];

// ---------------- small utility kernels ----------------
__global__ void zero_k(int* __restrict__ deg, float* __restrict__ asum, int n){
    int t = blockIdx.x * blockDim.x + threadIdx.x;
    if (t < n * 16) asum[t] = 0.f;
    if (t < n + 1)  deg[t]  = 0;
}

// per-edge: count in-degree + accumulate edge_attr sums by dst (4 threads/edge)
__global__ void deg_attr_k(const int* __restrict__ dst, const float* __restrict__ ea,
                           int* __restrict__ deg, float* __restrict__ asum, int E){
    int t = blockIdx.x * blockDim.x + threadIdx.x;
    int e = t >> 2, q = t & 3;
    if (e >= E) return;
    int d = dst[e];
    if (q == 0) atomicAdd(&deg[d], 1);
    float4 a = __ldg((const float4*)(ea + (size_t)e * 16 + q * 4));
    float* b = asum + (size_t)d * 16 + q * 4;
    atomicAdd(b + 0, a.x); atomicAdd(b + 1, a.y);
    atomicAdd(b + 2, a.z); atomicAdd(b + 3, a.w);
}

// single-block exclusive scan of deg -> rowptr (and cursor copy)
__global__ void scan_k(const int* __restrict__ deg, int* __restrict__ rowptr,
                       int* __restrict__ cursor, int n){
    __shared__ int ss[1024];
    int t = threadIdx.x;
    int chunk = (n + 1023) >> 10;
    int s = t * chunk, e = min(s + chunk, n);
    int a = 0;
    for (int i = s; i < e; i++) a += deg[i];
    ss[t] = a; __syncthreads();
    for (int ofs = 1; ofs < 1024; ofs <<= 1){
        int v = (t >= ofs) ? ss[t - ofs] : 0;
        __syncthreads();
        ss[t] += v;
        __syncthreads();
    }
    int run = (t == 0) ? 0 : ss[t - 1];
    for (int i = s; i < e; i++){ rowptr[i] = run; cursor[i] = run; run += deg[i]; }
    if (t == 1023) rowptr[n] = ss[1023];
}

__global__ void scatter_k(const int* __restrict__ src, const int* __restrict__ dst,
                          int* __restrict__ cursor, int* __restrict__ osrc,
                          int* __restrict__ oeid, int E){
    int e = blockIdx.x * blockDim.x + threadIdx.x;
    if (e >= E) return;
    int d = dst[e];
    int slot = atomicAdd(&cursor[d], 1);
    osrc[slot] = src[e];
    oeid[slot] = e;
}

__global__ void mean_attr_k(const float* __restrict__ asum, const int* __restrict__ deg,
                            float* __restrict__ mattr, int n){
    int t = blockIdx.x * blockDim.x + threadIdx.x;
    int node = t >> 2, q = t & 3;
    if (node >= n) return;
    float c = (float)max(deg[node], 1);
    float inv = 1.f / c;
    float4 a = *(const float4*)(asum + (size_t)node * 16 + q * 4);
    a.x *= inv; a.y *= inv; a.z *= inv; a.w *= inv;
    *(float4*)(mattr + (size_t)node * 16 + q * 4) = a;
}

// ---------------- GEMM: Y[n,COUT] = X[n,128] @ W[128,COUT] + B ----------------
// block: 256 thr = 32 tx (cols, TN=4) x 8 ty (row groups, TM=8). BM=64, BN=128, BK=16.
template<int COUT>
__global__ void __launch_bounds__(256) gemm128(const float* __restrict__ X,
                                               const float* __restrict__ W,
                                               const float* __restrict__ B,
                                               float* __restrict__ Y, int n){
    __shared__ float sxT[128 * 68];   // x transposed: [k][row], padded stride 68
    __shared__ float sw[16 * 128];
    int t = threadIdx.x;
    int tx = t & 31, ty = t >> 5;
    int row0 = blockIdx.y * 64;
    int cb   = blockIdx.x * 128;

    // load & transpose x tile (64 rows x 128 k)
    #pragma unroll
    for (int i = 0; i < 8; i++){
        int f = t + 256 * i;          // 0..2047 float4 slots
        int r = f >> 5, c4 = f & 31;
        float4 v = make_float4(0.f, 0.f, 0.f, 0.f);
        if (row0 + r < n) v = __ldg((const float4*)(X + (size_t)(row0 + r) * 128 + c4 * 4));
        sxT[(c4 * 4 + 0) * 68 + r] = v.x;
        sxT[(c4 * 4 + 1) * 68 + r] = v.y;
        sxT[(c4 * 4 + 2) * 68 + r] = v.z;
        sxT[(c4 * 4 + 3) * 68 + r] = v.w;
    }

    ull acc[8][2];
    #pragma unroll
    for (int r = 0; r < 8; r++){ acc[r][0] = 0ull; acc[r][1] = 0ull; }

    #pragma unroll 1
    for (int kt = 0; kt < 8; kt++){
        __syncthreads();
        #pragma unroll
        for (int i = 0; i < 2; i++){
            int f = t + 256 * i;       // 0..511 float4 slots
            int k = f >> 5, c4 = f & 31;
            *(float4*)&sw[k * 128 + c4 * 4] =
                __ldg((const float4*)(W + (size_t)(kt * 16 + k) * COUT + cb + c4 * 4));
        }
        __syncthreads();
        #pragma unroll
        for (int k = 0; k < 16; k++){
            int kk = kt * 16 + k;
            float4 xa = *(const float4*)&sxT[kk * 68 + ty * 8];
            float4 xb = *(const float4*)&sxT[kk * 68 + ty * 8 + 4];
            float4 wv = *(const float4*)&sw[k * 128 + tx * 4];
            ull w01 = packf2(wv.x, wv.y);
            ull w23 = packf2(wv.z, wv.w);
            float xs[8] = {xa.x, xa.y, xa.z, xa.w, xb.x, xb.y, xb.z, xb.w};
            #pragma unroll
            for (int r = 0; r < 8; r++){
                ull x2 = pack2(xs[r]);
                acc[r][0] = fma2(x2, w01, acc[r][0]);
                acc[r][1] = fma2(x2, w23, acc[r][1]);
            }
        }
    }

    float4 bv = __ldg((const float4*)(B + cb + tx * 4));
    #pragma unroll
    for (int r = 0; r < 8; r++){
        int row = row0 + ty * 8 + r;
        if (row < n){
            float2 p0 = unpack2(acc[r][0]);
            float2 p1 = unpack2(acc[r][1]);
            float4 o = make_float4(p0.x + bv.x, p0.y + bv.y, p1.x + bv.z, p1.y + bv.w);
            *(float4*)(Y + (size_t)row * COUT + cb + tx * 4) = o;
        }
    }
}

// ---------------- fused GATv2 edge pass: one warp per dst node, online softmax ----------------
// CH: per-head channels (32 or 64); heads=4; C = 4*CH. MEAN: average heads (final layer).
template<int CH, bool MEAN>
__global__ void __launch_bounds__(256) gat_edge(const float* __restrict__ xl,
                                                const float* __restrict__ xr,
                                                const float* __restrict__ We,
                                                const float* __restrict__ att,
                                                const float* __restrict__ bias,
                                                const float* __restrict__ eattr,
                                                const float* __restrict__ mattr,
                                                const int* __restrict__ rowptr,
                                                const int* __restrict__ srcs,
                                                const int* __restrict__ eids,
                                                float* __restrict__ out, int n){
    constexpr int C   = 4 * CH;
    constexpr int VPT = C / 32;      // 4 or 8 channels per lane
    constexpr int NP  = VPT / 4;     // float4 count
    __shared__ float sWe[16 * C];
    for (int i = threadIdx.x; i < 16 * C / 4; i += blockDim.x)
        ((float4*)sWe)[i] = __ldg(((const float4*)We) + i);
    __syncthreads();

    int warp = threadIdx.x >> 5;
    int lane = threadIdx.x & 31;
    int node = blockIdx.x * 8 + warp;
    if (node >= n) return;

    int head = lane >> 3, sub = lane & 7;
    float atv[VPT], xrv[VPT];
    #pragma unroll
    for (int p = 0; p < NP; p++){
        *(float4*)&atv[p * 4] = __ldg((const float4*)(att + head * CH + sub * VPT + p * 4));
        *(float4*)&xrv[p * 4] = __ldg((const float4*)(xr + (size_t)node * C + lane * VPT + p * 4));
    }

    float m = -3.0e38f, l = 0.f;
    float acc[VPT];
    #pragma unroll
    for (int j = 0; j < VPT; j++) acc[j] = 0.f;

    int start = rowptr[node], end = rowptr[node + 1];
    for (int idx = start; idx <= end; idx++){
        int s; const float* ea;
        if (idx < end){ s = srcs[idx]; ea = eattr + (size_t)eids[idx] * 16; }
        else          { s = node;      ea = mattr + (size_t)node * 16; }   // self loop

        float av[16];
        #pragma unroll
        for (int p = 0; p < 4; p++)
            *(float4*)&av[p * 4] = __ldg((const float4*)(ea + p * 4));

        float xlv[VPT];
        #pragma unroll
        for (int p = 0; p < NP; p++)
            *(float4*)&xlv[p * 4] = __ldg((const float4*)(xl + (size_t)s * C + lane * VPT + p * 4));

        // ee = ea @ We  (packed f32x2 FMAs, We from smem)
        ull e2[VPT / 2];
        #pragma unroll
        for (int j = 0; j < VPT / 2; j++) e2[j] = 0ull;
        const float* wbase = sWe + lane * VPT;
        #pragma unroll
        for (int k = 0; k < 16; k++){
            ull a2 = pack2(av[k]);
            #pragma unroll
            for (int j = 0; j < VPT / 2; j++){
                ull w = *(const ull*)(wbase + k * C + j * 2);
                e2[j] = fma2(a2, w, e2[j]);
            }
        }
        float ev[VPT];
        #pragma unroll
        for (int j = 0; j < VPT / 2; j++){
            float2 f = unpack2(e2[j]);
            ev[2 * j] = f.x; ev[2 * j + 1] = f.y;
        }

        // logit = sum_c leaky_relu(xl+xr+ee) * att
        float part = 0.f;
        #pragma unroll
        for (int j = 0; j < VPT; j++){
            float z = xlv[j] + xrv[j] + ev[j];
            z = (z > 0.f) ? z : 0.2f * z;
            part = fmaf(z, atv[j], part);
        }
        part += __shfl_xor_sync(0xffffffffu, part, 1);
        part += __shfl_xor_sync(0xffffffffu, part, 2);
        part += __shfl_xor_sync(0xffffffffu, part, 4);
        float logit = part;

        // online softmax update (per head; replicated across the 8-lane group)
        float mn = fmaxf(m, logit);
        float p  = __expf(logit - mn);
        float sc = __expf(m - mn);
        l = l * sc + p;
        #pragma unroll
        for (int j = 0; j < VPT; j++) acc[j] = fmaf(acc[j], sc, p * xlv[j]);
        m = mn;
    }

    float inv = 1.f / (l + 1e-16f);
    if (!MEAN){
        #pragma unroll
        for (int p = 0; p < NP; p++){
            float4 bo = __ldg((const float4*)(bias + lane * VPT + p * 4));
            float4 o;
            o.x = fmaxf(acc[p * 4 + 0] * inv + bo.x, 0.f);
            o.y = fmaxf(acc[p * 4 + 1] * inv + bo.y, 0.f);
            o.z = fmaxf(acc[p * 4 + 2] * inv + bo.z, 0.f);
            o.w = fmaxf(acc[p * 4 + 3] * inv + bo.w, 0.f);
            *(float4*)(out + (size_t)node * C + lane * VPT + p * 4) = o;
        }
    } else {
        float v[VPT];
        #pragma unroll
        for (int j = 0; j < VPT; j++){
            v[j] = acc[j] * inv;
            v[j] += __shfl_xor_sync(0xffffffffu, v[j], 8);
            v[j] += __shfl_xor_sync(0xffffffffu, v[j], 16);
        }
        if (lane < 8){
            #pragma unroll
            for (int p = 0; p < NP; p++){
                float4 bo = __ldg((const float4*)(bias + lane * VPT + p * 4));
                float4 o;
                o.x = fmaxf(0.25f * v[p * 4 + 0] + bo.x, 0.f);
                o.y = fmaxf(0.25f * v[p * 4 + 1] + bo.y, 0.f);
                o.z = fmaxf(0.25f * v[p * 4 + 2] + bo.z, 0.f);
                o.w = fmaxf(0.25f * v[p * 4 + 3] + bo.w, 0.f);
                *(float4*)(out + (size_t)node * CH + lane * VPT + p * 4) = o;
            }
        }
    }
}

// ---------------- global mean pool (batch is sorted; one block per graph) ----------------
__device__ __forceinline__ int lowerb(const int* a, int n, int v){
    int lo = 0, hi = n;
    while (lo < hi){ int md = (lo + hi) >> 1; if (a[md] < v) lo = md + 1; else hi = md; }
    return lo;
}

__global__ void pool_k(const float* __restrict__ h3, const int* __restrict__ batch,
                       float* __restrict__ gvec, int n){
    int g = blockIdx.x;
    int lo = lowerb(batch, n, g), hi = lowerb(batch, n, g + 1);
    int t = threadIdx.x;
    int ch = t & 63, rr = t >> 6;
    float s = 0.f;
    for (int i = lo + rr; i < hi; i += 4) s += h3[(size_t)i * 64 + ch];
    __shared__ float red[4][64];
    red[rr][ch] = s; __syncthreads();
    if (rr == 0){
        float tot = red[0][ch] + red[1][ch] + red[2][ch] + red[3][ch];
        float c = (float)max(hi - lo, 1);
        gvec[g * 64 + ch] = tot / c;
    }
}

__global__ void final_k(const float* __restrict__ gvec, const float* __restrict__ Wlin,
                        const float* __restrict__ blin, float* __restrict__ out){
    int t = threadIdx.x;
    int g = t >> 4, o = t & 15;
    float s = 0.f;
    #pragma unroll
    for (int k = 0; k < 64; k++) s = fmaf(gvec[g * 64 + k], Wlin[k * 16 + o], s);
    out[t] = s + blin[o];
}

// ---------------- host orchestration ----------------
extern "C" void kernel_launch(void* const* d_in, const int* in_sizes, int n_in,
                              void* d_out, int out_size){
    const float* x     = (const float*)d_in[0];
    const int*   eidx  = (const int*)  d_in[1];
    const int*   batch = (const int*)  d_in[2];
    const float* eattr = (const float*)d_in[3];
    const float* Wl0 = (const float*)d_in[4],  *bl0 = (const float*)d_in[5];
    const float* Wr0 = (const float*)d_in[6],  *br0 = (const float*)d_in[7];
    const float* We0 = (const float*)d_in[8],  *att0= (const float*)d_in[9];
    const float* bo0 = (const float*)d_in[10];
    const float* Wlh = (const float*)d_in[11], *blh = (const float*)d_in[12];
    const float* Wrh = (const float*)d_in[13], *brh = (const float*)d_in[14];
    const float* Weh = (const float*)d_in[15], *atth= (const float*)d_in[16];
    const float* boh = (const float*)d_in[17];
    const float* Wlf = (const float*)d_in[18], *blf = (const float*)d_in[19];
    const float* Wrf = (const float*)d_in[20], *brf = (const float*)d_in[21];
    const float* Wef = (const float*)d_in[22], *attf= (const float*)d_in[23];
    const float* bof = (const float*)d_in[24];
    const float* Wlin= (const float*)d_in[25], *blin= (const float*)d_in[26];

    int N = in_sizes[0] / 128;
    int E = in_sizes[1] / 2;
    const int* src = eidx;
    const int* dst = eidx + E;

    float *xl, *xr, *h1, *h2, *h3, *asum, *mattr, *gvec;
    int *deg, *rowptr, *cursor, *osrc, *oeid;
    cudaGetSymbolAddress((void**)&xl,     g_xl);
    cudaGetSymbolAddress((void**)&xr,     g_xr);
    cudaGetSymbolAddress((void**)&h1,     g_h1);
    cudaGetSymbolAddress((void**)&h2,     g_h2);
    cudaGetSymbolAddress((void**)&h3,     g_h3);
    cudaGetSymbolAddress((void**)&asum,   g_asum);
    cudaGetSymbolAddress((void**)&mattr,  g_mattr);
    cudaGetSymbolAddress((void**)&gvec,   g_gvec);
    cudaGetSymbolAddress((void**)&deg,    g_deg);
    cudaGetSymbolAddress((void**)&rowptr, g_rowptr);
    cudaGetSymbolAddress((void**)&cursor, g_cursor);
    cudaGetSymbolAddress((void**)&osrc,   g_srcs);
    cudaGetSymbolAddress((void**)&oeid,   g_eids);

    // ---- graph prep (CSR by dst + mean edge-attr for self-loops) ----
    zero_k     <<<(N * 16 + 255) / 256, 256>>>(deg, asum, N);
    deg_attr_k <<<(E * 4 + 255) / 256, 256>>>(dst, eattr, deg, asum, E);
    scan_k     <<<1, 1024>>>(deg, rowptr, cursor, N);
    scatter_k  <<<(E + 255) / 256, 256>>>(src, dst, cursor, osrc, oeid, E);
    mean_attr_k<<<(N * 4 + 255) / 256, 256>>>(asum, deg, mattr, N);

    dim3 g1(1, (N + 63) / 64), g2(2, (N + 63) / 64);
    int  eb = (N + 7) / 8;

    // ---- layer 0 ----
    gemm128<128><<<g1, 256>>>(x, Wl0, bl0, xl, N);
    gemm128<128><<<g1, 256>>>(x, Wr0, br0, xr, N);
    gat_edge<32, false><<<eb, 256>>>(xl, xr, We0, att0, bo0, eattr, mattr,
                                     rowptr, osrc, oeid, h1, N);
    // ---- layer 1 ----
    gemm128<128><<<g1, 256>>>(h1, Wlh, blh, xl, N);
    gemm128<128><<<g1, 256>>>(h1, Wrh, brh, xr, N);
    gat_edge<32, false><<<eb, 256>>>(xl, xr, Weh, atth, boh, eattr, mattr,
                                     rowptr, osrc, oeid, h2, N);
    // ---- layer 2 (mean over heads) ----
    gemm128<256><<<g2, 256>>>(h2, Wlf, blf, xl, N);
    gemm128<256><<<g2, 256>>>(h2, Wrf, brf, xr, N);
    gat_edge<64, true><<<eb, 256>>>(xl, xr, Wef, attf, bof, eattr, mattr,
                                    rowptr, osrc, oeid, h3, N);

    // ---- pool + final linear ----
    pool_k <<<64, 256>>>(h3, batch, gvec, N);
    final_k<<<1, 1024>>>(gvec, Wlin, blin, (float*)d_out);
}